// round 1
// baseline (speedup 1.0000x reference)
#include <cuda_runtime.h>
#include <cub/cub.cuh>

#define KBINS 10000
#define MAXN  8400000
#define SCAN_ITEMS 10   // 1024 * 10 >= KBINS

// ------------------------- static device scratch (no allocs) ----------------
__device__ __align__(16) int   g_iota[MAXN];
__device__ __align__(16) int   g_pasc[MAXN];   // idx_asc (stable asc sort by duration)
__device__ __align__(16) int   g_sdur[MAXN];   // sorted durations (ascending)
__device__ __align__(16) float g_expg2[MAXN];  // exp(log_h[idx_desc[p]]) at desc position p
__device__ __align__(16) float g_e2f[MAXN];    // events[idx_desc[p]] at desc position p
__device__ int    g_cnt[KBINS];
__device__ int    g_off[KBINS];                // N - 2*S[k] - C[k]
__device__ float  g_expg_sum[KBINS];
__device__ float  g_ev_sum[KBINS];
__device__ float  g_base[KBINS];
__device__ int    g_totE;
__device__ double g_mse;
__device__ unsigned char g_cub_temp[160u * 1024u * 1024u];

// ------------------------- kernels ------------------------------------------
__global__ void k_init(int N) {
    int i = blockIdx.x * blockDim.x + threadIdx.x;
    int stride = gridDim.x * blockDim.x;
    for (int j = i; j < N; j += stride) g_iota[j] = j;
    for (int j = i; j < KBINS; j += stride) {
        g_cnt[j] = 0; g_expg_sum[j] = 0.f; g_ev_sum[j] = 0.f;
    }
    if (i == 0) { g_totE = 0; g_mse = 0.0; }
}

__global__ void k_hist(const int* __restrict__ dur, const int* __restrict__ ev, int N) {
    __shared__ int sh[KBINS];
    __shared__ int sred[32];
    for (int i = threadIdx.x; i < KBINS; i += blockDim.x) sh[i] = 0;
    __syncthreads();
    int te = 0;
    for (int i = blockIdx.x * blockDim.x + threadIdx.x; i < N; i += gridDim.x * blockDim.x) {
        atomicAdd(&sh[dur[i]], 1);
        te += ev[i];
    }
    __syncthreads();
    for (int i = threadIdx.x; i < KBINS; i += blockDim.x) {
        int c = sh[i];
        if (c) atomicAdd(&g_cnt[i], c);
    }
    // reduce event total
    for (int o = 16; o; o >>= 1) te += __shfl_down_sync(0xffffffffu, te, o);
    if ((threadIdx.x & 31) == 0) sred[threadIdx.x >> 5] = te;
    __syncthreads();
    if (threadIdx.x < 32) {
        int nw = blockDim.x >> 5;
        int v = (threadIdx.x < nw) ? sred[threadIdx.x] : 0;
        for (int o = 16; o; o >>= 1) v += __shfl_down_sync(0xffffffffu, v, o);
        if (threadIdx.x == 0) atomicAdd(&g_totE, v);
    }
}

// exclusive prefix sum of counts -> offsets off[k] = N - 2*S[k] - C[k]
__global__ void k_scan(int N) {
    __shared__ int s[1024];
    int tid = threadIdx.x;
    int loc[SCAN_ITEMS];
    int run = 0;
#pragma unroll
    for (int i = 0; i < SCAN_ITEMS; i++) {
        int k = tid * SCAN_ITEMS + i;
        int c = (k < KBINS) ? g_cnt[k] : 0;
        loc[i] = run;    // exclusive within thread
        run += c;
    }
    s[tid] = run;
    __syncthreads();
    for (int off = 1; off < 1024; off <<= 1) {
        int v = (tid >= off) ? s[tid - off] : 0;
        __syncthreads();
        s[tid] += v;
        __syncthreads();
    }
    int excl = tid ? s[tid - 1] : 0;
#pragma unroll
    for (int i = 0; i < SCAN_ITEMS; i++) {
        int k = tid * SCAN_ITEMS + i;
        if (k < KBINS) {
            int Sk = excl + loc[i];
            g_off[k] = N - 2 * Sk - g_cnt[k];
        }
    }
}

// For asc position j: a = idx_asc[j]; its desc position jd = j + off[sortedDur[j]].
// Write expg2[jd] = exp(log_h[a]); e2f[jd] = events[a].
__global__ void k_gather(const float* __restrict__ lh, const int* __restrict__ ev, int N) {
    int tid = blockIdx.x * blockDim.x + threadIdx.x;
    int Nv = N & ~3;
    int j = tid * 4;
    if (j < Nv) {
        int4 a = *reinterpret_cast<const int4*>(g_pasc + j);
        int4 k = *reinterpret_cast<const int4*>(g_sdur + j);
        float h0 = __ldg(lh + a.x), h1 = __ldg(lh + a.y);
        float h2 = __ldg(lh + a.z), h3 = __ldg(lh + a.w);
        int e0 = __ldg(ev + a.x), e1 = __ldg(ev + a.y);
        int e2 = __ldg(ev + a.z), e3 = __ldg(ev + a.w);
        int o0 = g_off[k.x], o1 = g_off[k.y], o2 = g_off[k.z], o3 = g_off[k.w];
        g_expg2[j + 0 + o0] = expf(h0); g_e2f[j + 0 + o0] = (float)e0;
        g_expg2[j + 1 + o1] = expf(h1); g_e2f[j + 1 + o1] = (float)e1;
        g_expg2[j + 2 + o2] = expf(h2); g_e2f[j + 2 + o2] = (float)e2;
        g_expg2[j + 3 + o3] = expf(h3); g_e2f[j + 3 + o3] = (float)e3;
    }
    int t = Nv + tid;  // tail (<4 elements)
    if (t < N) {
        int a = g_pasc[t];
        int k = g_sdur[t];
        int o = g_off[k];
        g_expg2[t + o] = expf(lh[a]);
        g_e2f[t + o]  = (float)ev[a];
    }
}

// segment sums keyed by ORIGINAL durations of the desc-permuted values
__global__ void k_segsum(const int* __restrict__ dur, int N) {
    extern __shared__ float sm[];
    float* sE = sm;
    float* sV = sm + KBINS;
    for (int i = threadIdx.x; i < KBINS; i += blockDim.x) { sE[i] = 0.f; sV[i] = 0.f; }
    __syncthreads();
    for (int p = blockIdx.x * blockDim.x + threadIdx.x; p < N; p += gridDim.x * blockDim.x) {
        int k = dur[p];
        atomicAdd(&sE[k], g_expg2[p]);
        atomicAdd(&sV[k], g_e2f[p]);
    }
    __syncthreads();
    for (int i = threadIdx.x; i < KBINS; i += blockDim.x) {
        float a = sE[i], b = sV[i];
        if (a != 0.f) atomicAdd(&g_expg_sum[i], a);
        if (b != 0.f) atomicAdd(&g_ev_sum[i],   b);
    }
}

// risk[k] = sum_{k'>=k} expg_sum[k'];  base[k] = risk>0 ? ev_sum/risk : 0
__global__ void k_base() {
    __shared__ float s[1024];
    int tid = threadIdx.x;
    float loc[SCAN_ITEMS];
    float run = 0.f;
#pragma unroll
    for (int i = 0; i < SCAN_ITEMS; i++) {
        int m = tid * SCAN_ITEMS + i;
        int k = KBINS - 1 - m;
        float v = (k >= 0) ? g_expg_sum[k] : 0.f;
        run += v;
        loc[i] = run;    // inclusive within thread (reversed order)
    }
    s[tid] = run;
    __syncthreads();
    for (int off = 1; off < 1024; off <<= 1) {
        float v = (tid >= off) ? s[tid - off] : 0.f;
        __syncthreads();
        s[tid] += v;
        __syncthreads();
    }
    float excl = tid ? s[tid - 1] : 0.f;
#pragma unroll
    for (int i = 0; i < SCAN_ITEMS; i++) {
        int m = tid * SCAN_ITEMS + i;
        int k = KBINS - 1 - m;
        if (k >= 0) {
            float risk = excl + loc[i];
            g_base[k] = (risk > 0.f) ? (g_ev_sum[k] / risk) : 0.f;
        }
    }
}

__global__ void k_mse(int N) {
    double acc = 0.0;
    for (int j = blockIdx.x * blockDim.x + threadIdx.x; j < N; j += gridDim.x * blockDim.x) {
        int a = g_pasc[j];
        int k = g_sdur[j];
        float t = g_base[k] * g_expg2[j] - g_e2f[a];
        acc += (double)(t * t);
    }
    __shared__ double sd[32];
    for (int o = 16; o; o >>= 1) acc += __shfl_down_sync(0xffffffffu, acc, o);
    if ((threadIdx.x & 31) == 0) sd[threadIdx.x >> 5] = acc;
    __syncthreads();
    if (threadIdx.x < 32) {
        int nw = blockDim.x >> 5;
        double v = (threadIdx.x < nw) ? sd[threadIdx.x] : 0.0;
        for (int o = 16; o; o >>= 1) v += __shfl_down_sync(0xffffffffu, v, o);
        if (threadIdx.x == 0) atomicAdd(&g_mse, v);
    }
}

__global__ void k_fin(float* out, int N) {
    out[0] = (g_totE == 0) ? 0.f : (float)(g_mse / (double)N);
}

// ------------------------- host launcher ------------------------------------
extern "C" void kernel_launch(void* const* d_in, const int* in_sizes, int n_in,
                              void* d_out, int out_size) {
    const float* lh  = (const float*)d_in[0];
    const int*   dur = (const int*)d_in[1];
    const int*   ev  = (const int*)d_in[2];
    int N = in_sizes[0];
    float* out = (float*)d_out;

    cudaFuncSetAttribute(k_segsum, cudaFuncAttributeMaxDynamicSharedMemorySize,
                         2 * KBINS * (int)sizeof(float));

    void *p_iota, *p_pasc, *p_sdur, *p_temp;
    cudaGetSymbolAddress(&p_iota, g_iota);
    cudaGetSymbolAddress(&p_pasc, g_pasc);
    cudaGetSymbolAddress(&p_sdur, g_sdur);
    cudaGetSymbolAddress(&p_temp, g_cub_temp);

    k_init<<<2048, 512>>>(N);
    k_hist<<<296, 1024>>>(dur, ev, N);

    size_t temp_bytes = sizeof(g_cub_temp);
    cub::DeviceRadixSort::SortPairs(p_temp, temp_bytes,
                                    dur, (int*)p_sdur,
                                    (const int*)p_iota, (int*)p_pasc,
                                    N, 0, 14);

    k_scan<<<1, 1024>>>(N);

    int gb = (((N + 3) / 4) + 255) / 256;
    k_gather<<<gb, 256>>>(lh, ev, N);

    k_segsum<<<296, 1024, 2 * KBINS * sizeof(float)>>>(dur, N);
    k_base<<<1, 1024>>>();
    k_mse<<<1184, 256>>>(N);
    k_fin<<<1, 1>>>(out, N);
}

// round 2
// speedup vs baseline: 1.6578x; 1.6578x over previous
#include <cuda_runtime.h>
#include <cub/cub.cuh>

#define KBINS 10000
#define MAXN  8400000
#define SCAN_ITEMS 10   // 1024 * 10 >= KBINS

// ------------------------- static device scratch (no allocs) ----------------
__device__ __align__(16) int           g_iota[MAXN];
__device__ __align__(16) int           g_pasc[MAXN];    // idx_asc (stable asc sort by duration)
__device__ __align__(16) int           g_sdur[MAXN];    // sorted durations (ascending)
__device__ __align__(16) unsigned int  g_packed[MAXN];  // lh bits with event in mantissa LSB
__device__ __align__(16) float         g_expg2[MAXN];   // exp(log_h[idx_desc[p]]) at desc pos p
__device__ __align__(16) unsigned char g_e2u8[MAXN];    // events[idx_desc[p]] at desc pos p
__device__ int    g_S[KBINS];                 // first asc index of bin k (nonempty bins only)
__device__ int    g_E[KBINS];                 // one-past-last asc index of bin k
__device__ float  g_expg_sum[KBINS];
__device__ float  g_ev_sum[KBINS];
__device__ float  g_base[KBINS];
__device__ int    g_totE;
__device__ double g_mse;
__device__ unsigned char g_cub_temp[160u * 1024u * 1024u];

// ------------------------- kernels ------------------------------------------
__global__ void k_init(int N) {
    int i = blockIdx.x * blockDim.x + threadIdx.x;
    int stride = gridDim.x * blockDim.x;
    for (int j = i; j < N; j += stride) g_iota[j] = j;
    for (int j = i; j < KBINS; j += stride) { g_expg_sum[j] = 0.f; g_ev_sum[j] = 0.f; }
    if (i == 0) { g_totE = 0; g_mse = 0.0; }
}

// pack (log_h, event) into one u32; accumulate total events
__global__ void k_pack(const float* __restrict__ lh, const int* __restrict__ ev, int N) {
    __shared__ int sred[32];
    int te = 0;
    int stride = gridDim.x * blockDim.x;
    for (int i = blockIdx.x * blockDim.x + threadIdx.x; i < N; i += stride) {
        unsigned int b = __float_as_uint(lh[i]);
        int e = ev[i] & 1;
        g_packed[i] = (b & 0xFFFFFFFEu) | (unsigned)e;
        te += e;
    }
    for (int o = 16; o; o >>= 1) te += __shfl_down_sync(0xffffffffu, te, o);
    if ((threadIdx.x & 31) == 0) sred[threadIdx.x >> 5] = te;
    __syncthreads();
    if (threadIdx.x < 32) {
        int nw = blockDim.x >> 5;
        int v = (threadIdx.x < nw) ? sred[threadIdx.x] : 0;
        for (int o = 16; o; o >>= 1) v += __shfl_down_sync(0xffffffffu, v, o);
        if (threadIdx.x == 0) atomicAdd(&g_totE, v);
    }
}

// detect run boundaries of sorted durations -> S[k], E[k] (nonempty bins only)
__global__ void k_bounds(int N) {
    int i = blockIdx.x * blockDim.x + threadIdx.x;
    if (i >= N) return;
    int k = g_sdur[i];
    if (i == 0 || g_sdur[i - 1] != k) g_S[k] = i;
    if (i == N - 1 || g_sdur[i + 1] != k) g_E[k] = i + 1;
}

// For asc position j: a = idx_asc[j]; desc position jd = j + N - S[k] - E[k].
// Write expg2[jd] = exp(log_h[a]); e2u8[jd] = events[a].
__global__ void k_gather(int N) {
    int tid = blockIdx.x * blockDim.x + threadIdx.x;
    int Nv = N & ~3;
    int j = tid * 4;
    if (j < Nv) {
        int4 a = *reinterpret_cast<const int4*>(g_pasc + j);
        int4 k = *reinterpret_cast<const int4*>(g_sdur + j);
        unsigned int p0 = __ldg(g_packed + a.x), p1 = __ldg(g_packed + a.y);
        unsigned int p2 = __ldg(g_packed + a.z), p3 = __ldg(g_packed + a.w);
        int o0 = N - g_S[k.x] - g_E[k.x];
        int o1 = N - g_S[k.y] - g_E[k.y];
        int o2 = N - g_S[k.z] - g_E[k.z];
        int o3 = N - g_S[k.w] - g_E[k.w];
        g_expg2[j + 0 + o0] = expf(__uint_as_float(p0 & 0xFFFFFFFEu));
        g_expg2[j + 1 + o1] = expf(__uint_as_float(p1 & 0xFFFFFFFEu));
        g_expg2[j + 2 + o2] = expf(__uint_as_float(p2 & 0xFFFFFFFEu));
        g_expg2[j + 3 + o3] = expf(__uint_as_float(p3 & 0xFFFFFFFEu));
        g_e2u8[j + 0 + o0] = (unsigned char)(p0 & 1u);
        g_e2u8[j + 1 + o1] = (unsigned char)(p1 & 1u);
        g_e2u8[j + 2 + o2] = (unsigned char)(p2 & 1u);
        g_e2u8[j + 3 + o3] = (unsigned char)(p3 & 1u);
    }
    int t = Nv + tid;  // tail
    if (t < N) {
        int a = g_pasc[t];
        int k = g_sdur[t];
        unsigned int pl = g_packed[a];
        int o = N - g_S[k] - g_E[k];
        g_expg2[t + o] = expf(__uint_as_float(pl & 0xFFFFFFFEu));
        g_e2u8[t + o]  = (unsigned char)(pl & 1u);
    }
}

// segment sums keyed by ORIGINAL durations of the desc-permuted values
__global__ void k_segsum(const int* __restrict__ dur, int N) {
    extern __shared__ float sm[];
    float* sE = sm;
    int*   sV = (int*)(sm + KBINS);
    for (int i = threadIdx.x; i < KBINS; i += blockDim.x) { sE[i] = 0.f; sV[i] = 0; }
    __syncthreads();
    for (int p = blockIdx.x * blockDim.x + threadIdx.x; p < N; p += gridDim.x * blockDim.x) {
        int k = dur[p];
        atomicAdd(&sE[k], g_expg2[p]);
        int e = (int)g_e2u8[p];
        if (e) atomicAdd(&sV[k], 1);
    }
    __syncthreads();
    for (int i = threadIdx.x; i < KBINS; i += blockDim.x) {
        float a = sE[i]; int b = sV[i];
        if (a != 0.f) atomicAdd(&g_expg_sum[i], a);
        if (b)        atomicAdd(&g_ev_sum[i], (float)b);
    }
}

// risk[k] = sum_{k'>=k} expg_sum[k'];  base[k] = risk>0 ? ev_sum/risk : 0
__global__ void k_base() {
    __shared__ float s[1024];
    int tid = threadIdx.x;
    float loc[SCAN_ITEMS];
    float run = 0.f;
#pragma unroll
    for (int i = 0; i < SCAN_ITEMS; i++) {
        int m = tid * SCAN_ITEMS + i;
        int k = KBINS - 1 - m;
        float v = (k >= 0) ? g_expg_sum[k] : 0.f;
        run += v;
        loc[i] = run;    // inclusive within thread (reversed order)
    }
    s[tid] = run;
    __syncthreads();
    for (int off = 1; off < 1024; off <<= 1) {
        float v = (tid >= off) ? s[tid - off] : 0.f;
        __syncthreads();
        s[tid] += v;
        __syncthreads();
    }
    float excl = tid ? s[tid - 1] : 0.f;
#pragma unroll
    for (int i = 0; i < SCAN_ITEMS; i++) {
        int m = tid * SCAN_ITEMS + i;
        int k = KBINS - 1 - m;
        if (k >= 0) {
            float risk = excl + loc[i];
            g_base[k] = (risk > 0.f) ? (g_ev_sum[k] / risk) : 0.f;
        }
    }
}

// sum of x^2 - 2*x*e over j, with x = base[sdur[j]]*expg2[j], e = e2u8[pasc[j]]
// (the +sum(e^2) = totE term is added in k_fin)
__global__ void k_mse(int N) {
    double acc = 0.0;
    for (int j = blockIdx.x * blockDim.x + threadIdx.x; j < N; j += gridDim.x * blockDim.x) {
        int k = g_sdur[j];
        int a = g_pasc[j];
        float x = g_base[k] * g_expg2[j];
        float e = (float)g_e2u8[a];
        acc += (double)(x * (x - 2.f * e));
    }
    __shared__ double sd[32];
    for (int o = 16; o; o >>= 1) acc += __shfl_down_sync(0xffffffffu, acc, o);
    if ((threadIdx.x & 31) == 0) sd[threadIdx.x >> 5] = acc;
    __syncthreads();
    if (threadIdx.x < 32) {
        int nw = blockDim.x >> 5;
        double v = (threadIdx.x < nw) ? sd[threadIdx.x] : 0.0;
        for (int o = 16; o; o >>= 1) v += __shfl_down_sync(0xffffffffu, v, o);
        if (threadIdx.x == 0) atomicAdd(&g_mse, v);
    }
}

__global__ void k_fin(float* out, int N) {
    double mse = (g_mse + (double)g_totE) / (double)N;
    out[0] = (g_totE == 0) ? 0.f : (float)mse;
}

// ------------------------- host launcher ------------------------------------
extern "C" void kernel_launch(void* const* d_in, const int* in_sizes, int n_in,
                              void* d_out, int out_size) {
    const float* lh  = (const float*)d_in[0];
    const int*   dur = (const int*)d_in[1];
    const int*   ev  = (const int*)d_in[2];
    int N = in_sizes[0];
    float* out = (float*)d_out;

    size_t seg_smem = KBINS * (sizeof(float) + sizeof(int));
    cudaFuncSetAttribute(k_segsum, cudaFuncAttributeMaxDynamicSharedMemorySize,
                         (int)seg_smem);

    void *p_iota, *p_pasc, *p_sdur, *p_temp;
    cudaGetSymbolAddress(&p_iota, g_iota);
    cudaGetSymbolAddress(&p_pasc, g_pasc);
    cudaGetSymbolAddress(&p_sdur, g_sdur);
    cudaGetSymbolAddress(&p_temp, g_cub_temp);

    k_init<<<2048, 512>>>(N);
    k_pack<<<1184, 256>>>(lh, ev, N);

    size_t temp_bytes = sizeof(g_cub_temp);
    cub::DeviceRadixSort::SortPairs(p_temp, temp_bytes,
                                    dur, (int*)p_sdur,
                                    (const int*)p_iota, (int*)p_pasc,
                                    N, 0, 14);

    k_bounds<<<(N + 511) / 512, 512>>>(N);

    int gb = (((N + 3) / 4) + 255) / 256;
    k_gather<<<gb, 256>>>(N);

    k_segsum<<<296, 1024, seg_smem>>>(dur, N);
    k_base<<<1, 1024>>>();
    k_mse<<<1184, 256>>>(N);
    k_fin<<<1, 1>>>(out, N);
}

// round 4
// speedup vs baseline: 1.7581x; 1.0605x over previous
#include <cuda_runtime.h>
#include <cub/cub.cuh>

#define KBINS 10000
#define MAXN  8400000
#define SCAN_ITEMS 10   // 1024 * 10 >= KBINS

// ------------------------- static device scratch (no allocs) ----------------
__device__ __align__(16) int           g_iota[MAXN];
__device__ __align__(16) int           g_pasc[MAXN];    // idx_asc (stable asc sort by duration)
__device__ __align__(16) int           g_sdur[MAXN];    // sorted durations (ascending)
__device__ __align__(16) unsigned int  g_packed[MAXN];  // lh bits with event in mantissa LSB
__device__ __align__(16) float         g_expg2[MAXN];   // exp(log_h[idx_desc[p]]) at desc pos p
__device__ __align__(16) unsigned char g_e2u8[MAXN];    // events[idx_desc[p]] at desc pos p
__device__ int    g_S[KBINS];                 // first asc index of bin k (nonempty bins only)
__device__ int    g_E[KBINS];                 // one-past-last asc index of bin k
__device__ float  g_expg_sum[KBINS];
__device__ float  g_ev_sum[KBINS];
__device__ float  g_base[KBINS];
__device__ float  g_totE;                     // computed in k_base from ev_sum bins
__device__ double g_mse;                      // reset in k_base, accumulated in k_mse
__device__ unsigned char g_cub_temp[160u * 1024u * 1024u];

// ------------------------- kernels ------------------------------------------
// pack (log_h,event)->u32, iota, zero the bins (consumed by k_fused two launches later)
__global__ void k_pack_init(const float* __restrict__ lh, const int* __restrict__ ev, int N) {
    int stride = gridDim.x * blockDim.x;
    int gtid = blockIdx.x * blockDim.x + threadIdx.x;
    for (int i = gtid; i < N; i += stride) {
        unsigned int b = __float_as_uint(lh[i]);
        int e = ev[i] & 1;
        g_packed[i] = (b & 0xFFFFFFFEu) | (unsigned)e;
        g_iota[i] = i;
    }
    for (int j = gtid; j < KBINS; j += stride) { g_expg_sum[j] = 0.f; g_ev_sum[j] = 0.f; }
}

// detect run boundaries of sorted durations -> S[k], E[k] (nonempty bins only)
__global__ void k_bounds(int N) {
    int i = blockIdx.x * blockDim.x + threadIdx.x;
    if (i >= N) return;
    int k = g_sdur[i];
    if (i == 0 || g_sdur[i - 1] != k) g_S[k] = i;
    if (i == N - 1 || g_sdur[i + 1] != k) g_E[k] = i + 1;
}

// Fused gather + scatter + segment-sum.
// For asc position j: a = pasc[j], bin k = sdur[j], desc pos pd = j + N - S[k] - E[k].
// expg2[pd] = exp(lh[a]); e2u8[pd] = ev[a]; accumulate (dur[pd] -> expg, e) into bins.
__global__ void k_fused(const int* __restrict__ dur, int N) {
    extern __shared__ float sm[];
    float* sE = sm;                 // expg sums per bin
    int*   sV = (int*)(sm + KBINS); // event counts per bin
    for (int i = threadIdx.x; i < KBINS; i += blockDim.x) { sE[i] = 0.f; sV[i] = 0; }
    __syncthreads();

    int stride = gridDim.x * blockDim.x;
    int Nv = N >> 2;                // number of full int4 groups
    for (int g = blockIdx.x * blockDim.x + threadIdx.x; g < Nv; g += stride) {
        int j = g * 4;
        int4 a = *reinterpret_cast<const int4*>(g_pasc + j);
        int4 k = *reinterpret_cast<const int4*>(g_sdur + j);
        unsigned int p0 = __ldg(g_packed + a.x), p1 = __ldg(g_packed + a.y);
        unsigned int p2 = __ldg(g_packed + a.z), p3 = __ldg(g_packed + a.w);
        int o0 = N - g_S[k.x] - g_E[k.x];
        int o1 = N - g_S[k.y] - g_E[k.y];
        int o2 = N - g_S[k.z] - g_E[k.z];
        int o3 = N - g_S[k.w] - g_E[k.w];
        float x0 = __expf(__uint_as_float(p0 & 0xFFFFFFFEu));
        float x1 = __expf(__uint_as_float(p1 & 0xFFFFFFFEu));
        float x2 = __expf(__uint_as_float(p2 & 0xFFFFFFFEu));
        float x3 = __expf(__uint_as_float(p3 & 0xFFFFFFFEu));
        int pd0 = j + 0 + o0, pd1 = j + 1 + o1, pd2 = j + 2 + o2, pd3 = j + 3 + o3;
        g_expg2[pd0] = x0; g_expg2[pd1] = x1; g_expg2[pd2] = x2; g_expg2[pd3] = x3;
        g_e2u8[pd0] = (unsigned char)(p0 & 1u);
        g_e2u8[pd1] = (unsigned char)(p1 & 1u);
        g_e2u8[pd2] = (unsigned char)(p2 & 1u);
        g_e2u8[pd3] = (unsigned char)(p3 & 1u);
        int kk0 = __ldg(dur + pd0), kk1 = __ldg(dur + pd1);
        int kk2 = __ldg(dur + pd2), kk3 = __ldg(dur + pd3);
        atomicAdd(&sE[kk0], x0); if (p0 & 1u) atomicAdd(&sV[kk0], 1);
        atomicAdd(&sE[kk1], x1); if (p1 & 1u) atomicAdd(&sV[kk1], 1);
        atomicAdd(&sE[kk2], x2); if (p2 & 1u) atomicAdd(&sV[kk2], 1);
        atomicAdd(&sE[kk3], x3); if (p3 & 1u) atomicAdd(&sV[kk3], 1);
    }
    // tail (<4 elements), handled by first few threads of block 0
    if (blockIdx.x == 0 && threadIdx.x < (N & 3)) {
        int t = (N & ~3) + threadIdx.x;
        int a = g_pasc[t];
        int k = g_sdur[t];
        unsigned int pl = g_packed[a];
        int pd = t + N - g_S[k] - g_E[k];
        float x = __expf(__uint_as_float(pl & 0xFFFFFFFEu));
        g_expg2[pd] = x;
        g_e2u8[pd]  = (unsigned char)(pl & 1u);
        int kk = dur[pd];
        atomicAdd(&sE[kk], x); if (pl & 1u) atomicAdd(&sV[kk], 1);
    }
    __syncthreads();
    for (int i = threadIdx.x; i < KBINS; i += blockDim.x) {
        float a = sE[i]; int b = sV[i];
        if (a != 0.f) atomicAdd(&g_expg_sum[i], a);
        if (b)        atomicAdd(&g_ev_sum[i], (float)b);
    }
}

// risk[k] = sum_{k'>=k} expg_sum[k'];  base[k] = risk>0 ? ev_sum/risk : 0
// Also: g_totE = sum_k ev_sum[k]  (== total events), and reset g_mse for k_mse.
__global__ void k_base() {
    __shared__ float s[1024];
    __shared__ float s2[32];
    int tid = threadIdx.x;
    float loc[SCAN_ITEMS];
    float run = 0.f;
    float evt = 0.f;
#pragma unroll
    for (int i = 0; i < SCAN_ITEMS; i++) {
        int m = tid * SCAN_ITEMS + i;
        int k = KBINS - 1 - m;
        float v = (k >= 0) ? g_expg_sum[k] : 0.f;
        if (k >= 0) evt += g_ev_sum[k];
        run += v;
        loc[i] = run;    // inclusive within thread (reversed order)
    }
    s[tid] = run;
    __syncthreads();
    for (int off = 1; off < 1024; off <<= 1) {
        float v = (tid >= off) ? s[tid - off] : 0.f;
        __syncthreads();
        s[tid] += v;
        __syncthreads();
    }
    float excl = tid ? s[tid - 1] : 0.f;
#pragma unroll
    for (int i = 0; i < SCAN_ITEMS; i++) {
        int m = tid * SCAN_ITEMS + i;
        int k = KBINS - 1 - m;
        if (k >= 0) {
            float risk = excl + loc[i];
            g_base[k] = (risk > 0.f) ? (g_ev_sum[k] / risk) : 0.f;
        }
    }
    // reduce total events
    for (int o = 16; o; o >>= 1) evt += __shfl_down_sync(0xffffffffu, evt, o);
    if ((tid & 31) == 0) s2[tid >> 5] = evt;
    __syncthreads();
    if (tid < 32) {
        float v = s2[tid];
        for (int o = 16; o; o >>= 1) v += __shfl_down_sync(0xffffffffu, v, o);
        if (tid == 0) { g_totE = v; g_mse = 0.0; }
    }
}

// sum of x^2 - 2*x*e over j, with x = base[sdur[j]]*expg2[j], e = e2u8[pasc[j]]
// (the +sum(e) = totE term added in k_fin)
__global__ void k_mse(int N) {
    double acc = 0.0;
    int stride = gridDim.x * blockDim.x;
    int Nv = N >> 2;
    for (int g = blockIdx.x * blockDim.x + threadIdx.x; g < Nv; g += stride) {
        int j = g * 4;
        int4 k = *reinterpret_cast<const int4*>(g_sdur + j);
        int4 a = *reinterpret_cast<const int4*>(g_pasc + j);
        float4 xg = *reinterpret_cast<const float4*>(g_expg2 + j);
        float x0 = g_base[k.x] * xg.x;
        float x1 = g_base[k.y] * xg.y;
        float x2 = g_base[k.z] * xg.z;
        float x3 = g_base[k.w] * xg.w;
        float e0 = (float)__ldg(g_e2u8 + a.x);
        float e1 = (float)__ldg(g_e2u8 + a.y);
        float e2 = (float)__ldg(g_e2u8 + a.z);
        float e3 = (float)__ldg(g_e2u8 + a.w);
        float s = x0 * (x0 - 2.f * e0) + x1 * (x1 - 2.f * e1)
                + x2 * (x2 - 2.f * e2) + x3 * (x3 - 2.f * e3);
        acc += (double)s;
    }
    if (blockIdx.x == 0 && threadIdx.x < (N & 3)) {
        int t = (N & ~3) + threadIdx.x;
        float x = g_base[g_sdur[t]] * g_expg2[t];
        float e = (float)g_e2u8[g_pasc[t]];
        acc += (double)(x * (x - 2.f * e));
    }
    __shared__ double sd[32];
    for (int o = 16; o; o >>= 1) acc += __shfl_down_sync(0xffffffffu, acc, o);
    if ((threadIdx.x & 31) == 0) sd[threadIdx.x >> 5] = acc;
    __syncthreads();
    if (threadIdx.x < 32) {
        int nw = blockDim.x >> 5;
        double v = (threadIdx.x < nw) ? sd[threadIdx.x] : 0.0;
        for (int o = 16; o; o >>= 1) v += __shfl_down_sync(0xffffffffu, v, o);
        if (threadIdx.x == 0) atomicAdd(&g_mse, v);
    }
}

__global__ void k_fin(float* out, int N) {
    double mse = (g_mse + (double)g_totE) / (double)N;
    out[0] = (g_totE == 0.f) ? 0.f : (float)mse;
}

// ------------------------- host launcher ------------------------------------
extern "C" void kernel_launch(void* const* d_in, const int* in_sizes, int n_in,
                              void* d_out, int out_size) {
    const float* lh  = (const float*)d_in[0];
    const int*   dur = (const int*)d_in[1];
    const int*   ev  = (const int*)d_in[2];
    int N = in_sizes[0];
    float* out = (float*)d_out;

    size_t seg_smem = KBINS * (sizeof(float) + sizeof(int));
    cudaFuncSetAttribute(k_fused, cudaFuncAttributeMaxDynamicSharedMemorySize,
                         (int)seg_smem);

    void *p_iota, *p_pasc, *p_sdur, *p_temp;
    cudaGetSymbolAddress(&p_iota, g_iota);
    cudaGetSymbolAddress(&p_pasc, g_pasc);
    cudaGetSymbolAddress(&p_sdur, g_sdur);
    cudaGetSymbolAddress(&p_temp, g_cub_temp);

    k_pack_init<<<1184, 256>>>(lh, ev, N);

    size_t temp_bytes = sizeof(g_cub_temp);
    cub::DeviceRadixSort::SortPairs(p_temp, temp_bytes,
                                    dur, (int*)p_sdur,
                                    (const int*)p_iota, (int*)p_pasc,
                                    N, 0, 14);

    k_bounds<<<(N + 511) / 512, 512>>>(N);

    k_fused<<<296, 1024, seg_smem>>>(dur, N);
    k_base<<<1, 1024>>>();
    k_mse<<<1184, 256>>>(N);
    k_fin<<<1, 1>>>(out, N);
}